// round 12
// baseline (speedup 1.0000x reference)
#include <cuda_runtime.h>
#include <math.h>

#define DIM 192
#define NB 12
#define BLKV 4096
#define THREADS 256
#define FULLM 0xffffffffu
#define NEG_INF (-3.402823466e+38f)

// accumulators: [0]=sum(p*g) [1]=sum(p*p) [2]=sum(g*g) [3]=loss_cl
__device__ double g_acc[4] = {0.0, 0.0, 0.0, 0.0};
__device__ unsigned g_count = 0;

__device__ __forceinline__ float warp_sum(float v) {
#pragma unroll
    for (int o = 16; o; o >>= 1) v += __shfl_xor_sync(FULLM, v, o);
    return v;
}

// ---------------------------------------------------------------------------
// Thread (x,y) owns the 16-voxel z-column. lane = (x&1)*16 + y:
//   y+-1 : lane+-1 shfl     x^1 : lane^16 shfl (always a valid x neighbor)
//   other x : published smem column, 1 guarded LDS
// gt is binary: its whole column is a 16-bit mask (bitwise erode=AND cross,
// dilate=OR box, delta = e & ~d, skel |= delta) -- exact vs f32 reference.
// Per erosion level ONE publish (f32 e_k 16 STS + bits b_k 1 STS) + ONE sync;
// both the dilate of level k and the erode to level k+1 read that publish.
// Buffers alternate 0/1; WAR safety comes from one-phase barrier distance.
// ---------------------------------------------------------------------------

// f32 erode: min over z+-1 (regs), x (shfl + smem), y (shfl); +inf pad
__device__ __forceinline__ void erode_f32(const float (&v)[16], float (&e)[16],
                                          const float* __restrict__ fb,
                                          int to, bool xv, int y) {
#pragma unroll
    for (int k = 0; k < 16; k++) {
        float m = v[k];
        if (k > 0)   m = fminf(m, v[k - 1]);
        if (k < 15)  m = fminf(m, v[k + 1]);
        m = fminf(m, __shfl_xor_sync(FULLM, v[k], 16));
        float o = fb[(k << 8) + to];
        if (xv) m = fminf(m, o);
        float yu = __shfl_up_sync(FULLM, v[k], 1);
        if (y > 0)  m = fminf(m, yu);
        float yd = __shfl_down_sync(FULLM, v[k], 1);
        if (y < 15) m = fminf(m, yd);
        e[k] = m;
    }
}

// f32 dilate (3x3x3 max, -inf pad) fused with skel init/update.
template <bool FIRST>
__device__ __forceinline__ void dilate_upd_f32(const float (&e)[16], const float (&prev)[16],
                                               float (&skel)[16],
                                               const float* __restrict__ fb,
                                               int to, bool xv, int y) {
    float xo0 = fb[to];
    float xo_m1 = NEG_INF;
#pragma unroll
    for (int k = 0; k < 16; k++) {
        float xo_p1 = (k < 15) ? fb[((k + 1) << 8) + to] : NEG_INF;
        // own z-max
        float mzk = e[k];
        if (k > 0)   mzk = fmaxf(mzk, e[k - 1]);
        if (k < 15)  mzk = fmaxf(mzk, e[k + 1]);
        // partner column z-max via one shfl of own z-max
        float m = fmaxf(mzk, __shfl_xor_sync(FULLM, mzk, 16));
        // other-x column z-max via rolling LDS window
        float zo = fmaxf(xo0, fmaxf(xo_m1, xo_p1));
        if (xv) m = fmaxf(m, zo);
        // y-pass on completed xz-max
        float yu = __shfl_up_sync(FULLM, m, 1);
        float yd = __shfl_down_sync(FULLM, m, 1);
        float d = m;
        if (y > 0)  d = fmaxf(d, yu);
        if (y < 15) d = fmaxf(d, yd);
        float delta = fmaxf(prev[k] - d, 0.0f);
        if (FIRST) {
            skel[k] = delta;
        } else {
            float s = skel[k];
            skel[k] = s + fmaxf(delta - s * delta, 0.0f);
        }
        xo_m1 = xo0; xo0 = xo_p1;
    }
}

// bits erode (AND 7-cross, pads=1) reading published bits
__device__ __forceinline__ unsigned erode_bits(unsigned cur, const unsigned* __restrict__ ib,
                                               int to, bool xv, int y) {
    unsigned m = cur & ((cur << 1) | 1u) & ((cur >> 1) | 0x8000u);
    m &= __shfl_xor_sync(FULLM, cur, 16);
    unsigned ox = ib[to];
    if (xv) m &= ox;
    unsigned yu = __shfl_up_sync(FULLM, cur, 1);
    if (y > 0)  m &= yu;
    unsigned yd = __shfl_down_sync(FULLM, cur, 1);
    if (y < 15) m &= yd;
    return m & 0xFFFFu;
}

// bits dilate (OR 3x3x3 box, pads=0); other-x dz recomputed from published e-bits
__device__ __forceinline__ unsigned dilate_bits(unsigned e, const unsigned* __restrict__ ib,
                                                int to, bool xv, int y) {
    unsigned dz = e | (e << 1) | (e >> 1);
    unsigned dx = dz | __shfl_xor_sync(FULLM, dz, 16);
    unsigned ox = ib[to];
    if (xv) dx |= ox | (ox << 1) | (ox >> 1);
    unsigned d = dx;
    unsigned yu = __shfl_up_sync(FULLM, dx, 1);
    if (y > 0)  d |= yu;
    unsigned yd = __shfl_down_sync(FULLM, dx, 1);
    if (y < 15) d |= yd;
    return d & 0xFFFFu;
}

__device__ __forceinline__ double block_tversky(double tp, double fn, double fp) {
    const double s = 1e-8;
    double ab = fp + fn + s;
    double alpha = 0.5 + 0.5 * (fp + s) / ab;
    double beta  = 0.5 + 0.5 * (fn + s) / ab;
    return 1.0 - (tp + s) / (tp + alpha * fp + beta * fn + s);
}

extern __shared__ float smem[];

__global__ void __launch_bounds__(THREADS, 3)
loss_main_kernel(const float* __restrict__ pred, const float* __restrict__ gt,
                 const float* __restrict__ w1, const float* __restrict__ w2,
                 float* __restrict__ out, int nblk) {
    float* fb0 = smem;                                  // f32 exchange, even phases
    float* fb1 = smem + BLKV;                           // f32 exchange, odd phases
    unsigned* ib0 = (unsigned*)(smem + 2 * BLKV);       // bits exchange, even
    unsigned* ib1 = ib0 + 256;                          // bits exchange, odd
    __shared__ float red[8][6];
    __shared__ unsigned last_flag;

    int t = threadIdx.x;
    int b = blockIdx.x;
    int by = b % NB;
    int bx = (b / NB) % NB;
    int bz = (b / (NB * NB)) % NB;
    int n  = b / (NB * NB * NB);

    long base = (long)n * DIM * DIM * DIM
              + (long)(bz * 16) * DIM * DIM
              + (long)(bx * 16) * DIM
              + (long)(by * 16);

    int x = t >> 4;
    int y = t & 15;
    bool xv = (x & 1) ? (x < 15) : (x > 0);
    int to = xv ? ((x & 1) ? t + 16 : t - 16) : t;
    int lane = t & 31, w = t >> 5;

    // ---- load: pred->f32 col, gt->bitmask; dice partials banked early ----
    float p[16];
    unsigned b0m = 0;
    {
        float pg = 0.f, pp = 0.f;
#pragma unroll
        for (int k = 0; k < 16; k++) {
            long gi = base + (long)k * DIM * DIM + x * DIM + y;
            float gv = gt[gi];
            float pv = pred[gi];
            p[k] = pv;
            if (gv != 0.0f) { b0m |= (1u << k); pg += pv; }
            pp += pv * pv;
        }
        float gg = (float)__popc(b0m);
        float s0 = warp_sum(pg), s1 = warp_sum(pp), s2 = warp_sum(gg);
        if (lane == 0) { red[w][0] = s0; red[w][1] = s1; red[w][2] = s2; }
    }

    // NOTE: reference's boundary conv kernel is -(ones.at[13].set(26)) -- all
    // taps negative -- so (b > 0.1) is identically false, loss_bdr == 0. Dropped.

    // ---- merged skeleton pipeline: 5 publish+sync phases ----
    float e1[16], skel[16];
    unsigned bA = b0m, bB, bskel = 0;

    // P0: publish e0=p/b0; erode -> e1/bB
#pragma unroll
    for (int k = 0; k < 16; k++) fb0[(k << 8) + t] = p[k];
    ib0[t] = bA;
    __syncthreads();
    erode_f32(p, e1, fb0, to, xv, y);
    bB = erode_bits(bA, ib0, to, xv, y);

    // P1: publish e1/bB; skel init with prev=p/bA; erode -> p=e2 / bA=b2
#pragma unroll
    for (int k = 0; k < 16; k++) fb1[(k << 8) + t] = e1[k];
    ib1[t] = bB;
    __syncthreads();
    dilate_upd_f32<true>(e1, p, skel, fb1, to, xv, y);
    bskel |= bA & ~dilate_bits(bB, ib1, to, xv, y);
    erode_f32(e1, p, fb1, to, xv, y);
    bA = erode_bits(bB, ib1, to, xv, y);

    // P2: publish e2(p)/b2(bA); update prev=e1/bB; erode -> e1=e3 / bB=b3
#pragma unroll
    for (int k = 0; k < 16; k++) fb0[(k << 8) + t] = p[k];
    ib0[t] = bA;
    __syncthreads();
    dilate_upd_f32<false>(p, e1, skel, fb0, to, xv, y);
    bskel |= bB & ~dilate_bits(bA, ib0, to, xv, y);
    erode_f32(p, e1, fb0, to, xv, y);
    bB = erode_bits(bA, ib0, to, xv, y);

    // P3: publish e3(e1)/b3(bB); update prev=p/bA; erode -> p=e4 / bA=b4
#pragma unroll
    for (int k = 0; k < 16; k++) fb1[(k << 8) + t] = e1[k];
    ib1[t] = bB;
    __syncthreads();
    dilate_upd_f32<false>(e1, p, skel, fb1, to, xv, y);
    bskel |= bA & ~dilate_bits(bB, ib1, to, xv, y);
    erode_f32(e1, p, fb1, to, xv, y);
    bA = erode_bits(bB, ib1, to, xv, y);

    // P4: publish e4(p)/b4(bA); final update prev=e1/bB (no erode)
#pragma unroll
    for (int k = 0; k < 16; k++) fb0[(k << 8) + t] = p[k];
    ib0[t] = bA;
    __syncthreads();
    dilate_upd_f32<false>(p, e1, skel, fb0, to, xv, y);
    bskel |= bB & ~dilate_bits(bA, ib0, to, xv, y);

    // ---- clDice tversky counts ----
    float tpc = 0.f, fnc = 0.f, fpc = 0.f;
#pragma unroll
    for (int k = 0; k < 16; k++) {
        float sp = skel[k];
        if ((bskel >> k) & 1u) {
            tpc += sp;
            fnc += 1.0f - sp;
        } else {
            fpc += sp;
        }
    }
    {
        float s3 = warp_sum(tpc), s4 = warp_sum(fnc), s5 = warp_sum(fpc);
        if (lane == 0) { red[w][3] = s3; red[w][4] = s4; red[w][5] = s5; }
    }
    __syncthreads();

    // ---- per-block accumulate + last-CTA finalize ----
    if (t == 0) {
        double s[6];
#pragma unroll
        for (int i = 0; i < 6; i++) {
            double acc = 0.0;
#pragma unroll
            for (int ww = 0; ww < 8; ww++) acc += (double)red[ww][i];
            s[i] = acc;
        }
        atomicAdd(&g_acc[0], s[0]);
        atomicAdd(&g_acc[1], s[1]);
        atomicAdd(&g_acc[2], s[2]);
        atomicAdd(&g_acc[3], block_tversky(s[3], s[4], s[5]));
        __threadfence();
        unsigned c = atomicAdd(&g_count, 1u);
        last_flag = (c == (unsigned)(nblk - 1)) ? 1u : 0u;
    }
    __syncthreads();

    if (last_flag && t == 0) {
        __threadfence();
        double pg = g_acc[0], pp = g_acc[1], gg = g_acc[2], cl = g_acc[3];
        double dice = 2.0 * pg / fmax(pp + gg, 1e-6);
        double dice_loss = 1.0 - dice;
        double w1s = (double)w1[0], w2s = (double)w2[0];
        double edge = (cl / (w2s * w2s)) / (2.0 * (double)nblk)
                    + log(1.0 + fabs(w1s) * fabs(w2s));
        out[0] = (float)((dice < 0.8) ? dice_loss : dice_loss + edge);
        // reset for the next (graph-replayed) call
        g_acc[0] = 0.0; g_acc[1] = 0.0; g_acc[2] = 0.0; g_acc[3] = 0.0;
        g_count = 0u;
        __threadfence();
    }
}

extern "C" void kernel_launch(void* const* d_in, const int* in_sizes, int n_in,
                              void* d_out, int out_size) {
    const float* pred = (const float*)d_in[0];
    const float* gt   = (const float*)d_in[1];
    const float* w1   = (const float*)d_in[2];
    const float* w2   = (const float*)d_in[3];
    float* out = (float*)d_out;

    int total = in_sizes[0];
    int N = total / (DIM * DIM * DIM);
    int nblk = N * NB * NB * NB;

    int smem_bytes = 2 * BLKV * (int)sizeof(float) + 512 * (int)sizeof(unsigned);
    cudaFuncSetAttribute(loss_main_kernel,
                         cudaFuncAttributeMaxDynamicSharedMemorySize, smem_bytes);

    loss_main_kernel<<<nblk, THREADS, smem_bytes>>>(pred, gt, w1, w2, out, nblk);
}